// round 6
// baseline (speedup 1.0000x reference)
#include <cuda_runtime.h>

// FindPeaks: 3x3 zero-padded peak detection, unfold/argmax tie-breaking:
//   peak <=> max(strict nbrs: idx 0..3) < c  &&  max(loose nbrs: idx 5..8) <= c
// out = peak ? c : 0.   [B,1,768,768] f32.
//
// R1: 1 float4/thread -> L1-bound, 34.5us.  R5: 4 rows/thread + shfl halos ->
// 25.6us, nothing saturated, occ 41.7% (56 regs) => latency-bound.
// R6: streaming 8 rows/thread with 5-row rolling buffer (prefetch dist 2) to
// cut live registers -> 5 CTAs/SM, and cut vertical re-reads (10 loads / 8 rows).

static constexpr int H = 768;
static constexpr int W = 768;
static constexpr int RPT = 8;                 // output rows per thread
static constexpr int SPAN = 128;              // floats per warp in x
static constexpr int XS = W / SPAN;           // 6 warp spans per row
static constexpr int YG = H / RPT;            // 96 row groups

__global__ __launch_bounds__(256) void find_peaks_kernel(
    const float* __restrict__ in, float* __restrict__ out, int n_img)
{
    int wg   = (blockIdx.x * blockDim.x + threadIdx.x) >> 5;
    int lane = threadIdx.x & 31;
    int total_warps = n_img * YG * XS;
    if (wg >= total_warps) return;

    int xs = wg % XS;
    int t  = wg / XS;
    int yg = t % YG;
    int b  = t / YG;
    int y0 = yg * RPT;
    int x  = xs * SPAN + lane * 4;

    const float* img   = in  + (size_t)b * H * W;
    float*       obase = out + (size_t)b * H * W + x;

    const bool has_l = (xs > 0);
    const bool has_r = (xs < XS - 1);

    // rolling buffer of 5 rows; slot s holds {float4, left halo, right halo}
    float4 v[5];
    float  lh[5], rh[5];

    // Load row y into slot s. y-bound check is warp-uniform; shuffles run
    // under full mask. s is a compile-time constant at every expansion.
#define LOADROW(ys, s)                                                       \
    do {                                                                     \
        int _y = (ys);                                                       \
        if ((unsigned)_y < (unsigned)H) {                                    \
            const float* _rp = img + (size_t)_y * W;                         \
            float4 _v = *reinterpret_cast<const float4*>(_rp + x);           \
            float _le = 0.0f, _re = 0.0f;                                    \
            if (lane == 0  && has_l) _le = _rp[x - 1];                       \
            if (lane == 31 && has_r) _re = _rp[x + 4];                       \
            float _lu = __shfl_up_sync(0xFFFFFFFFu,  _v.w, 1);               \
            float _rd = __shfl_down_sync(0xFFFFFFFFu, _v.x, 1);              \
            v[s]  = _v;                                                      \
            lh[s] = (lane == 0)  ? _le : _lu;                                \
            rh[s] = (lane == 31) ? _re : _rd;                                \
        } else {                                                             \
            v[s]  = make_float4(0.f, 0.f, 0.f, 0.f);                         \
            lh[s] = 0.f; rh[s] = 0.f;                                        \
        }                                                                    \
    } while (0)

    LOADROW(y0 - 1, 0);
    LOADROW(y0,     1);
    LOADROW(y0 + 1, 2);
    LOADROW(y0 + 2, 3);

    #pragma unroll
    for (int k = 0; k < RPT; k++) {
        // prefetch row y0+k+3 (used 2 iterations later); skip tail over-reads
        if (k < RPT - 2) LOADROW(y0 + k + 3, (k + 4) % 5);

        const int st = k % 5, sm = (k + 1) % 5, sb = (k + 2) % 5;

        float tw[6] = { lh[st], v[st].x, v[st].y, v[st].z, v[st].w, rh[st] };
        float mw[6] = { lh[sm], v[sm].x, v[sm].y, v[sm].z, v[sm].w, rh[sm] };
        float bw[6] = { lh[sb], v[sb].x, v[sb].y, v[sb].z, v[sb].w, rh[sb] };

        float4 o;
        float* op = &o.x;
        #pragma unroll
        for (int i = 0; i < 4; i++) {
            float c = mw[i + 1];
            // kernel idx 0..3 strictly < c; idx 5..8 <= c
            float ms = fmaxf(fmaxf(tw[i], tw[i + 1]), fmaxf(tw[i + 2], mw[i]));
            float ml = fmaxf(fmaxf(mw[i + 2], bw[i]), fmaxf(bw[i + 1], bw[i + 2]));
            op[i] = ((ms < c) & (ml <= c)) ? c : 0.0f;
        }
        *reinterpret_cast<float4*>(obase + (size_t)(y0 + k) * W) = o;
    }
#undef LOADROW
}

extern "C" void kernel_launch(void* const* d_in, const int* in_sizes, int n_in,
                              void* d_out, int out_size)
{
    const float* in = (const float*)d_in[0];
    float* out = (float*)d_out;
    int n_img = in_sizes[0] / (H * W);            // C==1
    int total_warps = n_img * YG * XS;            // 18432 for B=32
    int total_threads = total_warps * 32;
    int block = 256;
    int grid = (total_threads + block - 1) / block;
    find_peaks_kernel<<<grid, block>>>(in, out, n_img);
}

// round 9
// speedup vs baseline: 1.1378x; 1.1378x over previous
#include <cuda_runtime.h>

// FindPeaks: 3x3 zero-padded peak detection, unfold/argmax tie-breaking:
//   peak <=> max(strict nbrs: idx 0..3) < c  &&  max(loose nbrs: idx 5..8) <= c
// out = peak ? c : 0.   [B,1,768,768] f32.
//
// R5 (best): 4 rows/thread, 6 front-batched row loads, shfl halos -> 25.6us,
//   56 regs, occ 41.7%, nothing saturated => latency/occupancy-bound.
// R6: streaming buffer -> regs unchanged, MLP down, 26.4us. Reverted.
// R7-R9: R5 structure + block=128 + __launch_bounds__(128,10) forcing <=51
//   regs -> 10 CTAs/SM = 62.5% occ; direct float4 output, incremental ptrs.

static constexpr int H = 768;
static constexpr int W = 768;
static constexpr int RPT = 4;                 // output rows per thread
static constexpr int SPAN = 128;              // floats per warp in x
static constexpr int XS = W / SPAN;           // 6 warp spans per row
static constexpr int YG = H / RPT;            // 192 row groups

__global__ __launch_bounds__(128, 10) void find_peaks_kernel(
    const float* __restrict__ in, float* __restrict__ out, int n_img)
{
    int wg   = (blockIdx.x * blockDim.x + threadIdx.x) >> 5;  // global warp id
    int lane = threadIdx.x & 31;
    int total_warps = n_img * YG * XS;
    if (wg >= total_warps) return;

    int xs = wg % XS;
    int t  = wg / XS;
    int yg = t % YG;
    int b  = t / YG;
    int y0 = yg * RPT;
    int x  = xs * SPAN + lane * 4;

    const float* img = in + (size_t)b * H * W;

    const bool has_l = (xs > 0);
    const bool has_r = (xs < XS - 1);

    // 6 rows: y0-1 .. y0+4; lane float4 + halos via shfl (edges: scalar LDG).
    float4 v[RPT + 2];
    float  lh[RPT + 2], rh[RPT + 2];

    // Wide loads first, incremental pointer (y checks are warp-uniform).
    {
        const float* rp = img + (size_t)(y0 - 1) * W + x;
        #pragma unroll
        for (int k = 0; k < RPT + 2; k++) {
            int y = y0 + k - 1;
            v[k] = (y >= 0 && y < H) ? *reinterpret_cast<const float4*>(rp)
                                     : make_float4(0.f, 0.f, 0.f, 0.f);
            rp += W;
        }
    }

    // Halos.
    {
        const float* rp = img + (size_t)(y0 - 1) * W;
        #pragma unroll
        for (int k = 0; k < RPT + 2; k++) {
            int y = y0 + k - 1;
            float lu = __shfl_up_sync(0xFFFFFFFFu,  v[k].w, 1);
            float rd = __shfl_down_sync(0xFFFFFFFFu, v[k].x, 1);
            float le = 0.0f, re = 0.0f;
            if (y >= 0 && y < H) {
                if (lane == 0  && has_l) le = rp[x - 1];
                if (lane == 31 && has_r) re = rp[x + 4];
            }
            lh[k] = (lane == 0)  ? le : lu;
            rh[k] = (lane == 31) ? re : rd;
            rp += W;
        }
    }

    float* op = out + (size_t)b * H * W + (size_t)y0 * W + x;

    #pragma unroll
    for (int k = 0; k < RPT; k++) {
        float tw[6] = { lh[k],     v[k].x,   v[k].y,   v[k].z,   v[k].w,   rh[k]     };
        float mw[6] = { lh[k + 1], v[k+1].x, v[k+1].y, v[k+1].z, v[k+1].w, rh[k + 1] };
        float bw[6] = { lh[k + 2], v[k+2].x, v[k+2].y, v[k+2].z, v[k+2].w, rh[k + 2] };

        float4 o;
        {
            float c = mw[1];
            float ms = fmaxf(fmaxf(tw[0], tw[1]), fmaxf(tw[2], mw[0]));
            float ml = fmaxf(fmaxf(mw[2], bw[0]), fmaxf(bw[1], bw[2]));
            o.x = ((ms < c) & (ml <= c)) ? c : 0.0f;
        }
        {
            float c = mw[2];
            float ms = fmaxf(fmaxf(tw[1], tw[2]), fmaxf(tw[3], mw[1]));
            float ml = fmaxf(fmaxf(mw[3], bw[1]), fmaxf(bw[2], bw[3]));
            o.y = ((ms < c) & (ml <= c)) ? c : 0.0f;
        }
        {
            float c = mw[3];
            float ms = fmaxf(fmaxf(tw[2], tw[3]), fmaxf(tw[4], mw[2]));
            float ml = fmaxf(fmaxf(mw[4], bw[2]), fmaxf(bw[3], bw[4]));
            o.z = ((ms < c) & (ml <= c)) ? c : 0.0f;
        }
        {
            float c = mw[4];
            float ms = fmaxf(fmaxf(tw[3], tw[4]), fmaxf(tw[5], mw[3]));
            float ml = fmaxf(fmaxf(mw[5], bw[3]), fmaxf(bw[4], bw[5]));
            o.w = ((ms < c) & (ml <= c)) ? c : 0.0f;
        }
        *reinterpret_cast<float4*>(op) = o;
        op += W;
    }
}

extern "C" void kernel_launch(void* const* d_in, const int* in_sizes, int n_in,
                              void* d_out, int out_size)
{
    const float* in = (const float*)d_in[0];
    float* out = (float*)d_out;
    int n_img = in_sizes[0] / (H * W);            // C==1
    int total_warps = n_img * YG * XS;            // 36864 for B=32
    int total_threads = total_warps * 32;
    int block = 128;
    int grid = (total_threads + block - 1) / block;
    find_peaks_kernel<<<grid, block>>>(in, out, n_img);
}